// round 15
// baseline (speedup 1.0000x reference)
#include <cuda_runtime.h>
#include <cuda_bf16.h>
#include <cuda_fp16.h>

#define BATCH 8
#define NSEQ  2048
#define DIM   256
#define NROWS (BATCH * NSEQ)          // 16384
#define NEGV  (-999999.0f)

// ---------------- scratch (device globals; no allocation allowed) ----------
__device__ __half g_hT[(size_t)NROWS * DIM];            // h^T fp16 [b][d][j]
__device__ __nv_bfloat16 g_WT_hi[DIM * DIM];            // W^T split   [n][k]
__device__ __nv_bfloat16 g_WT_lo[DIM * DIM];
__device__ __nv_bfloat16 g_Hw_hi[DIM * DIM];            // Hw split    [n][k]
__device__ __nv_bfloat16 g_Hw_lo[DIM * DIM];
__device__ __half g_P[(size_t)NROWS * NSEQ];            // softmax P fp16 (67MB)
__device__ float g_asrc[NROWS];
__device__ float g_adst[NROWS];

__device__ __forceinline__ float fsigmoid(float x) {
    return __fdividef(1.0f, 1.0f + __expf(-x));
}

__device__ __forceinline__ unsigned smem_u32(const void* p) {
    unsigned a;
    asm("{ .reg .u64 t; cvta.to.shared.u64 t, %1; cvt.u32.u64 %0, t; }"
        : "=r"(a) : "l"(p));
    return a;
}

__device__ __forceinline__ void ldsm_x4(unsigned r[4], unsigned addr) {
    asm volatile("ldmatrix.sync.aligned.m8n8.x4.shared.b16 {%0,%1,%2,%3}, [%4];"
                 : "=r"(r[0]), "=r"(r[1]), "=r"(r[2]), "=r"(r[3]) : "r"(addr));
}

__device__ __forceinline__ void mma_bf16(float c[4], const unsigned a[4],
                                         unsigned b0, unsigned b1) {
    asm volatile("mma.sync.aligned.m16n8k16.row.col.f32.bf16.bf16.f32 "
                 "{%0,%1,%2,%3}, {%4,%5,%6,%7}, {%8,%9}, {%0,%1,%2,%3};"
                 : "+f"(c[0]), "+f"(c[1]), "+f"(c[2]), "+f"(c[3])
                 : "r"(a[0]), "r"(a[1]), "r"(a[2]), "r"(a[3]), "r"(b0), "r"(b1));
}

__device__ __forceinline__ void mma_f16(float c[4], const unsigned a[4],
                                        unsigned b0, unsigned b1) {
    asm volatile("mma.sync.aligned.m16n8k16.row.col.f32.f16.f16.f32 "
                 "{%0,%1,%2,%3}, {%4,%5,%6,%7}, {%8,%9}, {%0,%1,%2,%3};"
                 : "+f"(c[0]), "+f"(c[1]), "+f"(c[2]), "+f"(c[3])
                 : "r"(a[0]), "r"(a[1]), "r"(a[2]), "r"(a[3]), "r"(b0), "r"(b1));
}

__device__ __forceinline__ void split_bf16(float v, __nv_bfloat16& hi, __nv_bfloat16& lo) {
    hi = __float2bfloat16_rn(v);
    lo = __float2bfloat16_rn(v - __bfloat162float(hi));
}

__device__ __forceinline__ void cp_async16(unsigned saddr, const void* gptr) {
    asm volatile("cp.async.cg.shared.global [%0], [%1], 16;"
                 :: "r"(saddr), "l"(gptr) : "memory");
}
#define CP_COMMIT() asm volatile("cp.async.commit_group;" ::: "memory")
#define CP_WAIT(N)  asm volatile("cp.async.wait_group %0;" :: "n"(N) : "memory")

#define PITCHB 144

// ---------------- K0b: W^T split + Hw split ---------------------------------
__global__ __launch_bounds__(256) void k0b_splitW(const float* __restrict__ W,
                                                  const float* __restrict__ Hw)
{
    const int n = blockIdx.x;            // 0..255
    const int k = threadIdx.x;           // 0..255
    split_bf16(W[k * DIM + n], g_WT_hi[n * DIM + k], g_WT_lo[n * DIM + k]);
    split_bf16(Hw[n * DIM + k], g_Hw_hi[n * DIM + k], g_Hw_lo[n * DIM + k]);
}

// ---------------- K1: h = X @ W (bf16-split mma) + fused epilogue -----------
__global__ __launch_bounds__(256, 2) void k1_mma(const float* __restrict__ X,
                                                 const float* __restrict__ Ws)
{
    extern __shared__ char sm[];
    char* sA_hi = sm;
    char* sA_lo = sm + 9216;
    char* sB_hi = sm + 18432;
    char* sB_lo = sm + 55296;
    __shared__ float s_ws[2][DIM];

    const int t    = threadIdx.x;
    const int lane = t & 31;
    const int wid  = t >> 5;
    const int wm   = wid & 1;
    const int wn   = wid >> 1;
    const int m0   = blockIdx.x * 64;

    s_ws[0][t] = Ws[t];
    s_ws[1][t] = Ws[DIM + t];

    const unsigned lrow = (lane & 15);
    const unsigned lcol = (lane >> 4) << 4;
    const unsigned aBase0 = smem_u32(sA_hi) + (wm * 32 + lrow) * PITCHB + lcol;
    const unsigned bBase0 = smem_u32(sB_hi) + (wn * 64 + lrow) * PITCHB + lcol;

    float acc[2][8][4] = {};

    for (int kc = 0; kc < 4; kc++) {
        const int j0 = kc * 64;
        __syncthreads();
        #pragma unroll
        for (int q = 0; q < 2; q++) {
            const int idx = q * 256 + t;
            const int row = idx >> 3, seg = idx & 7;
            const float* gx = X + (size_t)(m0 + row) * DIM + j0 + seg * 8;
            float4 v0 = *(const float4*)gx;
            float4 v1 = *(const float4*)(gx + 4);
            union { __nv_bfloat16 h[8]; uint4 v; } Uh, Ul;
            split_bf16(v0.x, Uh.h[0], Ul.h[0]);
            split_bf16(v0.y, Uh.h[1], Ul.h[1]);
            split_bf16(v0.z, Uh.h[2], Ul.h[2]);
            split_bf16(v0.w, Uh.h[3], Ul.h[3]);
            split_bf16(v1.x, Uh.h[4], Ul.h[4]);
            split_bf16(v1.y, Uh.h[5], Ul.h[5]);
            split_bf16(v1.z, Uh.h[6], Ul.h[6]);
            split_bf16(v1.w, Uh.h[7], Ul.h[7]);
            const unsigned off = row * PITCHB + seg * 16;
            *(uint4*)(sA_hi + off) = Uh.v;
            *(uint4*)(sA_lo + off) = Ul.v;
        }
        #pragma unroll
        for (int q = 0; q < 8; q++) {
            const int idx = q * 256 + t;
            const int d = idx >> 3, seg = idx & 7;
            const size_t go = (size_t)d * DIM + j0 + seg * 8;
            const unsigned off = d * PITCHB + seg * 16;
            *(uint4*)(sB_hi + off) = *(const uint4*)(g_WT_hi + go);
            *(uint4*)(sB_lo + off) = *(const uint4*)(g_WT_lo + go);
        }
        __syncthreads();
        #pragma unroll
        for (int ks = 0; ks < 4; ks++) {
            unsigned ah[2][4], al[2][4];
            #pragma unroll
            for (int mt = 0; mt < 2; mt++) {
                ldsm_x4(ah[mt], aBase0 + mt * 16 * PITCHB + ks * 32);
                ldsm_x4(al[mt], aBase0 + 9216u + mt * 16 * PITCHB + ks * 32);
            }
            #pragma unroll
            for (int np = 0; np < 4; np++) {
                unsigned bh[4], bl[4];
                ldsm_x4(bh, bBase0 + np * 16 * PITCHB + ks * 32);
                ldsm_x4(bl, bBase0 + 36864u + np * 16 * PITCHB + ks * 32);
                #pragma unroll
                for (int mt = 0; mt < 2; mt++) {
                    mma_bf16(acc[mt][np*2+0], ah[mt], bh[0], bh[2]);
                    mma_bf16(acc[mt][np*2+1], ah[mt], bh[1], bh[3]);
                    mma_bf16(acc[mt][np*2+0], ah[mt], bl[0], bl[2]);
                    mma_bf16(acc[mt][np*2+1], ah[mt], bl[1], bl[3]);
                    mma_bf16(acc[mt][np*2+0], al[mt], bh[0], bh[2]);
                    mma_bf16(acc[mt][np*2+1], al[mt], bh[1], bh[3]);
                }
            }
        }
    }

    // ---- fused epilogue ----
    __syncthreads();
    __half* smT   = (__half*)sm;              // [col][row], pitch 72 halves
    float* partS  = (float*)(sm + 36864);
    float* partD  = (float*)(sm + 40960);

    float ps[2][2] = {}, pd[2][2] = {};
    #pragma unroll
    for (int mt = 0; mt < 2; mt++) {
        const int rA = wm * 32 + mt * 16 + (lane >> 2);
        const int rB = rA + 8;
        #pragma unroll
        for (int nf = 0; nf < 8; nf++) {
            const int c0 = wn * 64 + nf * 8 + (lane & 3) * 2;
            smT[(c0    ) * 72 + rA] = __float2half_rn(acc[mt][nf][0]);
            smT[(c0 + 1) * 72 + rA] = __float2half_rn(acc[mt][nf][1]);
            smT[(c0    ) * 72 + rB] = __float2half_rn(acc[mt][nf][2]);
            smT[(c0 + 1) * 72 + rB] = __float2half_rn(acc[mt][nf][3]);
            ps[mt][0] += acc[mt][nf][0] * s_ws[0][c0] + acc[mt][nf][1] * s_ws[0][c0 + 1];
            pd[mt][0] += acc[mt][nf][0] * s_ws[1][c0] + acc[mt][nf][1] * s_ws[1][c0 + 1];
            ps[mt][1] += acc[mt][nf][2] * s_ws[0][c0] + acc[mt][nf][3] * s_ws[0][c0 + 1];
            pd[mt][1] += acc[mt][nf][2] * s_ws[1][c0] + acc[mt][nf][3] * s_ws[1][c0 + 1];
        }
        const int slot = wn * 4 + (lane & 3);
        partS[rA * 16 + slot] = ps[mt][0];
        partD[rA * 16 + slot] = pd[mt][0];
        partS[rB * 16 + slot] = ps[mt][1];
        partD[rB * 16 + slot] = pd[mt][1];
    }
    __syncthreads();

    {
        const int b  = m0 >> 11;
        const int j0 = m0 & 2047;
        const int colg = t >> 3, seg = t & 7;
        #pragma unroll
        for (int k = 0; k < 8; k++) {
            const int col = colg + k * 32;
            uint4 v = *(const uint4*)((const char*)smT + col * 144 + seg * 16);
            *(uint4*)(g_hT + ((size_t)(b * DIM + col)) * NSEQ + j0 + seg * 8) = v;
        }
    }
    if (t < 64) {
        float s = 0.f, d = 0.f;
        #pragma unroll
        for (int k = 0; k < 16; k++) { s += partS[t * 16 + k]; d += partD[t * 16 + k]; }
        g_asrc[m0 + t] = s;
        g_adst[m0 + t] = d;
    }
}

// ---------------- K3: write I_A + full softmax P (single fp16) --------------
__global__ __launch_bounds__(256) void k3_ia_p(const int*   __restrict__ adj,
                                               const float* __restrict__ bsv,
                                               float*       __restrict__ outIA)
{
    const int i = blockIdx.x;
    const int b = blockIdx.y;
    const int t = threadIdx.x;
    const int lane = t & 31, warp = t >> 5;
    const int j0 = t * 8;
    const size_t rbase = ((size_t)b * NSEQ + i) * NSEQ;
    const float asrc = g_asrc[b * NSEQ + i];
    const float bs0  = bsv[0];

    int4 a0 = *(const int4*)(adj + rbase + j0);
    int4 a1 = *(const int4*)(adj + rbase + j0 + 4);
    const int av[8] = {a0.x, a0.y, a0.z, a0.w, a1.x, a1.y, a1.z, a1.w};
    float ad[8];
    *(float4*)(ad)     = *(const float4*)(g_adst + b * NSEQ + j0);
    *(float4*)(ad + 4) = *(const float4*)(g_adst + b * NSEQ + j0 + 4);

    float sc[8], iav[8];
    float mx = -3.0e38f;
    #pragma unroll
    for (int e = 0; e < 8; e++) {
        const int j = j0 + e;
        float x = asrc + ad[e] + bs0;
        float attn = (j < i) ? fsigmoid(x) : 0.0f;
        float ia = ((j == i) ? 1.0f : 0.0f) - attn;
        iav[e] = ia;
        float s = ((j <= i) && (av[e] == 1)) ? ia : NEGV;
        sc[e] = s;
        mx = fmaxf(mx, s);
    }
    *(float4*)(outIA + rbase + j0)     = *(float4*)(iav);
    *(float4*)(outIA + rbase + j0 + 4) = *(float4*)(iav + 4);

    __shared__ float redm[8], reds[8];
    #pragma unroll
    for (int o = 16; o > 0; o >>= 1) mx = fmaxf(mx, __shfl_xor_sync(0xffffffffu, mx, o));
    if (lane == 0) redm[warp] = mx;
    __syncthreads();
    float bm = redm[0];
    #pragma unroll
    for (int w = 1; w < 8; w++) bm = fmaxf(bm, redm[w]);

    float ex[8];
    float sum = 0.f;
    #pragma unroll
    for (int e = 0; e < 8; e++) { ex[e] = __expf(sc[e] - bm); sum += ex[e]; }
    #pragma unroll
    for (int o = 16; o > 0; o >>= 1) sum += __shfl_xor_sync(0xffffffffu, sum, o);
    if (lane == 0) reds[warp] = sum;
    __syncthreads();
    float tot = 0.f;
    #pragma unroll
    for (int w = 0; w < 8; w++) tot += reds[w];
    const float inv = __fdividef(1.0f, tot);

    union { __half h[8]; uint4 v; } Up;
    #pragma unroll
    for (int e = 0; e < 8; e++) Up.h[e] = __float2half_rn(ex[e] * inv);
    *(uint4*)(g_P + rbase + j0) = Up.v;
}

// ---------------- K4: feat_out = P @ h + b — fp16 GEMM, N-split, 2 CTA/SM ---
// CTA: M=128, N=128, 256 threads (8 warps = 4m x 2n, warp tile m32 x n64).
// 3-stage cp.async pipeline, one barrier per chunk; grid (16, 2, 8) = 256 CTAs
// -> 2 CTAs/SM (regs 120*256*2 = 61K, smem 2*110592 = 221KB). Extra P reads
// from the N-split hit L2 (per-batch P slice = 8.4MB << 126MB L2).
// Buffer (36864 B): A(P) @0 (18432), B(hT) @18432 (18432).
#define KCH    64
#define BUF_SZ 36864u
#define NCHUNK (NSEQ / KCH)
__device__ __forceinline__ void k4_prefetch(int b, int i0, int n0, int j0, unsigned sb)
{
    const int t = threadIdx.x;
    #pragma unroll
    for (int q = 0; q < 4; q++) {
        const int idx = q * 256 + t;
        const int row = idx >> 3, seg = idx & 7;
        const size_t go = ((size_t)(b * NSEQ + i0 + row)) * NSEQ + j0 + seg * 8;
        cp_async16(sb + row * PITCHB + seg * 16, g_P + go);
    }
    #pragma unroll
    for (int q = 0; q < 4; q++) {
        const int idx = q * 256 + t;
        const int dl = idx >> 3, seg = idx & 7;
        const size_t go = ((size_t)(b * DIM + n0 + dl)) * NSEQ + j0 + seg * 8;
        cp_async16(sb + 18432u + dl * PITCHB + seg * 16, g_hT + go);
    }
}

__global__ __launch_bounds__(256, 2) void k4_mma(const float* __restrict__ bias,
                                                 float*       __restrict__ outFO)
{
    extern __shared__ char sm[];
    const int t    = threadIdx.x;
    const int lane = t & 31;
    const int wid  = t >> 5;
    const int wm   = wid & 3;           // 4 m-warps -> 32 rows each
    const int wn   = wid >> 2;          // 2 n-warps -> 64 cols each
    const int b    = blockIdx.z;
    const int i0   = blockIdx.x * 128;
    const int n0   = blockIdx.y * 128;

    const unsigned smb  = smem_u32(sm);
    const unsigned lrow = (lane & 15);
    const unsigned lcol = (lane >> 4) << 4;
    const unsigned aBase0 = smb + (wm * 32 + lrow) * PITCHB + lcol;
    const unsigned bBase0 = smb + 18432u + (wn * 64 + lrow) * PITCHB + lcol;

    float acc[2][8][4] = {};

    k4_prefetch(b, i0, n0, 0, smb);
    CP_COMMIT();
    k4_prefetch(b, i0, n0, KCH, smb + BUF_SZ);
    CP_COMMIT();

    for (int c = 0; c < NCHUNK; c++) {
        if (c == NCHUNK - 1) { CP_WAIT(0); } else { CP_WAIT(1); }
        __syncthreads();                       // chunk c visible to all warps

        const unsigned bufOff = (unsigned)(c % 3) * BUF_SZ;
        #pragma unroll
        for (int ks = 0; ks < 4; ks++) {
            unsigned ah[2][4];
            #pragma unroll
            for (int mt = 0; mt < 2; mt++)
                ldsm_x4(ah[mt], aBase0 + bufOff + mt * 16 * PITCHB + ks * 32);
            #pragma unroll
            for (int np = 0; np < 4; np++) {
                unsigned bh[4];
                ldsm_x4(bh, bBase0 + bufOff + np * 16 * PITCHB + ks * 32);
                #pragma unroll
                for (int mt = 0; mt < 2; mt++) {
                    mma_f16(acc[mt][np*2+0], ah[mt], bh[0], bh[2]);
                    mma_f16(acc[mt][np*2+1], ah[mt], bh[1], bh[3]);
                }
            }
        }

        if (c + 2 < NCHUNK) {                  // overwrites buf (c-1)%3: safe
            k4_prefetch(b, i0, n0, (c + 2) * KCH, smb + (unsigned)((c + 2) % 3) * BUF_SZ);
            CP_COMMIT();
        }
    }

    #pragma unroll
    for (int mt = 0; mt < 2; mt++) {
        const int row0 = i0 + wm * 32 + mt * 16 + (lane >> 2);
        #pragma unroll
        for (int nf = 0; nf < 8; nf++) {
            const int col = n0 + wn * 64 + nf * 8 + (lane & 3) * 2;
            const float b0 = bias[col], b1 = bias[col + 1];
            float2 v0 = make_float2(acc[mt][nf][0] + b0, acc[mt][nf][1] + b1);
            float2 v1 = make_float2(acc[mt][nf][2] + b0, acc[mt][nf][3] + b1);
            *(float2*)(outFO + ((size_t)(b * NSEQ + row0)) * DIM + col) = v0;
            *(float2*)(outFO + ((size_t)(b * NSEQ + row0 + 8)) * DIM + col) = v1;
        }
    }
}

// ---------------- K5: gate = sigmoid(X@Hw^T+Hb), blend, via mma.sync --------
__global__ __launch_bounds__(256, 2) void k5_mma(const float* __restrict__ X,
                                                 const float* __restrict__ Hb,
                                                 float*       __restrict__ out)
{
    extern __shared__ char sm[];
    char* sA_hi = sm;
    char* sA_lo = sm + 9216;
    char* sB_hi = sm + 18432;
    char* sB_lo = sm + 55296;

    const int t    = threadIdx.x;
    const int lane = t & 31;
    const int wid  = t >> 5;
    const int wm   = wid & 1;
    const int wn   = wid >> 1;
    const int m0   = blockIdx.x * 64;

    const unsigned lrow = (lane & 15);
    const unsigned lcol = (lane >> 4) << 4;
    const unsigned aBase0 = smem_u32(sA_hi) + (wm * 32 + lrow) * PITCHB + lcol;
    const unsigned bBase0 = smem_u32(sB_hi) + (wn * 64 + lrow) * PITCHB + lcol;

    float acc[2][8][4] = {};

    for (int kc = 0; kc < 4; kc++) {
        const int j0 = kc * 64;
        __syncthreads();
        #pragma unroll
        for (int q = 0; q < 2; q++) {
            const int idx = q * 256 + t;
            const int row = idx >> 3, seg = idx & 7;
            const float* gx = X + (size_t)(m0 + row) * DIM + j0 + seg * 8;
            float4 v0 = *(const float4*)gx;
            float4 v1 = *(const float4*)(gx + 4);
            union { __nv_bfloat16 h[8]; uint4 v; } Uh, Ul;
            split_bf16(v0.x, Uh.h[0], Ul.h[0]);
            split_bf16(v0.y, Uh.h[1], Ul.h[1]);
            split_bf16(v0.z, Uh.h[2], Ul.h[2]);
            split_bf16(v0.w, Uh.h[3], Ul.h[3]);
            split_bf16(v1.x, Uh.h[4], Ul.h[4]);
            split_bf16(v1.y, Uh.h[5], Ul.h[5]);
            split_bf16(v1.z, Uh.h[6], Ul.h[6]);
            split_bf16(v1.w, Uh.h[7], Ul.h[7]);
            const unsigned off = row * PITCHB + seg * 16;
            *(uint4*)(sA_hi + off) = Uh.v;
            *(uint4*)(sA_lo + off) = Ul.v;
        }
        #pragma unroll
        for (int q = 0; q < 8; q++) {
            const int idx = q * 256 + t;
            const int d = idx >> 3, seg = idx & 7;
            const size_t go = (size_t)d * DIM + j0 + seg * 8;
            const unsigned off = d * PITCHB + seg * 16;
            *(uint4*)(sB_hi + off) = *(const uint4*)(g_Hw_hi + go);
            *(uint4*)(sB_lo + off) = *(const uint4*)(g_Hw_lo + go);
        }
        __syncthreads();
        #pragma unroll
        for (int ks = 0; ks < 4; ks++) {
            unsigned ah[2][4], al[2][4];
            #pragma unroll
            for (int mt = 0; mt < 2; mt++) {
                ldsm_x4(ah[mt], aBase0 + mt * 16 * PITCHB + ks * 32);
                ldsm_x4(al[mt], aBase0 + 9216u + mt * 16 * PITCHB + ks * 32);
            }
            #pragma unroll
            for (int np = 0; np < 4; np++) {
                unsigned bh[4], bl[4];
                ldsm_x4(bh, bBase0 + np * 16 * PITCHB + ks * 32);
                ldsm_x4(bl, bBase0 + 36864u + np * 16 * PITCHB + ks * 32);
                #pragma unroll
                for (int mt = 0; mt < 2; mt++) {
                    mma_bf16(acc[mt][np*2+0], ah[mt], bh[0], bh[2]);
                    mma_bf16(acc[mt][np*2+1], ah[mt], bh[1], bh[3]);
                    mma_bf16(acc[mt][np*2+0], ah[mt], bl[0], bl[2]);
                    mma_bf16(acc[mt][np*2+1], ah[mt], bl[1], bl[3]);
                    mma_bf16(acc[mt][np*2+0], al[mt], bh[0], bh[2]);
                    mma_bf16(acc[mt][np*2+1], al[mt], bh[1], bh[3]);
                }
            }
        }
    }

    #pragma unroll
    for (int mt = 0; mt < 2; mt++) {
        const int row0 = m0 + wm * 32 + mt * 16 + (lane >> 2);
        #pragma unroll
        for (int nf = 0; nf < 8; nf++) {
            const int col = wn * 64 + nf * 8 + (lane & 3) * 2;
            const float hb0 = Hb[col], hb1 = Hb[col + 1];
            #pragma unroll
            for (int rr = 0; rr < 2; rr++) {
                const size_t o = (size_t)(row0 + rr * 8) * DIM + col;
                float2 fo = *(const float2*)(out + o);
                float2 xv = *(const float2*)(X + o);
                float g0 = fsigmoid(acc[mt][nf][rr*2+0] + hb0);
                float g1 = fsigmoid(acc[mt][nf][rr*2+1] + hb1);
                float e0 = (fo.x > 0.0f) ? fo.x : expm1f(fo.x);
                float e1 = (fo.y > 0.0f) ? fo.y : expm1f(fo.y);
                float2 r;
                r.x = g0 * e0 + (1.0f - g0) * xv.x;
                r.y = g1 * e1 + (1.0f - g1) * xv.y;
                *(float2*)(out + o) = r;
            }
        }
    }
}

// ---------------- launch ----------------------------------------------------
extern "C" void kernel_launch(void* const* d_in, const int* in_sizes, int n_in,
                              void* d_out, int out_size)
{
    const float* feat = (const float*)d_in[0];
    const int*   adj  = (const int*)  d_in[1];
    const float* W    = (const float*)d_in[2];
    const float* bvec = (const float*)d_in[3];
    const float* Ws   = (const float*)d_in[4];
    const float* bs   = (const float*)d_in[5];
    const float* Hw   = (const float*)d_in[6];
    const float* Hb   = (const float*)d_in[7];

    float* out   = (float*)d_out;                      // (B,N,256)
    float* outIA = out + (size_t)NROWS * DIM;          // (B,1,N,N)

    cudaFuncSetAttribute(k1_mma, cudaFuncAttributeMaxDynamicSharedMemorySize, 92160);
    cudaFuncSetAttribute(k4_mma, cudaFuncAttributeMaxDynamicSharedMemorySize, 3 * BUF_SZ);
    cudaFuncSetAttribute(k5_mma, cudaFuncAttributeMaxDynamicSharedMemorySize, 92160);

    k0b_splitW<<<DIM, DIM>>>(W, Hw);
    k1_mma   <<<NROWS / 64, 256, 92160>>>(feat, Ws);
    k3_ia_p  <<<dim3(NSEQ, BATCH), 256>>>(adj, bs, outIA);
    k4_mma   <<<dim3(NSEQ / 128, 2, BATCH), 256, 3 * BUF_SZ>>>(bvec, out);
    k5_mma   <<<NROWS / 64, 256, 92160>>>(feat, Hb, out);
}

// round 16
// speedup vs baseline: 1.1140x; 1.1140x over previous
#include <cuda_runtime.h>
#include <cuda_bf16.h>
#include <cuda_fp16.h>

#define BATCH 8
#define NSEQ  2048
#define DIM   256
#define NROWS (BATCH * NSEQ)          // 16384
#define NEGV  (-999999.0f)

// ---------------- scratch (device globals; no allocation allowed) ----------
__device__ __half g_hT[(size_t)NROWS * DIM];            // h^T fp16 [b][d][j]
__device__ __nv_bfloat16 g_WT_hi[DIM * DIM];            // W^T split   [n][k]
__device__ __nv_bfloat16 g_WT_lo[DIM * DIM];
__device__ __half g_Hw_f16[DIM * DIM];                  // Hw fp16     [n][k]
__device__ __half g_P[(size_t)NROWS * NSEQ];            // softmax P fp16 (67MB)
__device__ float g_asrc[NROWS];
__device__ float g_adst[NROWS];

__device__ __forceinline__ float fsigmoid(float x) {
    return __fdividef(1.0f, 1.0f + __expf(-x));
}

__device__ __forceinline__ unsigned smem_u32(const void* p) {
    unsigned a;
    asm("{ .reg .u64 t; cvta.to.shared.u64 t, %1; cvt.u32.u64 %0, t; }"
        : "=r"(a) : "l"(p));
    return a;
}

__device__ __forceinline__ void ldsm_x4(unsigned r[4], unsigned addr) {
    asm volatile("ldmatrix.sync.aligned.m8n8.x4.shared.b16 {%0,%1,%2,%3}, [%4];"
                 : "=r"(r[0]), "=r"(r[1]), "=r"(r[2]), "=r"(r[3]) : "r"(addr));
}

__device__ __forceinline__ void mma_bf16(float c[4], const unsigned a[4],
                                         unsigned b0, unsigned b1) {
    asm volatile("mma.sync.aligned.m16n8k16.row.col.f32.bf16.bf16.f32 "
                 "{%0,%1,%2,%3}, {%4,%5,%6,%7}, {%8,%9}, {%0,%1,%2,%3};"
                 : "+f"(c[0]), "+f"(c[1]), "+f"(c[2]), "+f"(c[3])
                 : "r"(a[0]), "r"(a[1]), "r"(a[2]), "r"(a[3]), "r"(b0), "r"(b1));
}

__device__ __forceinline__ void mma_f16(float c[4], const unsigned a[4],
                                        unsigned b0, unsigned b1) {
    asm volatile("mma.sync.aligned.m16n8k16.row.col.f32.f16.f16.f32 "
                 "{%0,%1,%2,%3}, {%4,%5,%6,%7}, {%8,%9}, {%0,%1,%2,%3};"
                 : "+f"(c[0]), "+f"(c[1]), "+f"(c[2]), "+f"(c[3])
                 : "r"(a[0]), "r"(a[1]), "r"(a[2]), "r"(a[3]), "r"(b0), "r"(b1));
}

__device__ __forceinline__ void split_bf16(float v, __nv_bfloat16& hi, __nv_bfloat16& lo) {
    hi = __float2bfloat16_rn(v);
    lo = __float2bfloat16_rn(v - __bfloat162float(hi));
}

__device__ __forceinline__ void cp_async16(unsigned saddr, const void* gptr) {
    asm volatile("cp.async.cg.shared.global [%0], [%1], 16;"
                 :: "r"(saddr), "l"(gptr) : "memory");
}
#define CP_COMMIT() asm volatile("cp.async.commit_group;" ::: "memory")
#define CP_WAIT(N)  asm volatile("cp.async.wait_group %0;" :: "n"(N) : "memory")

#define PITCHB 144

// ---------------- K0b: W^T bf16 split + Hw fp16 -----------------------------
__global__ __launch_bounds__(256) void k0b_splitW(const float* __restrict__ W,
                                                  const float* __restrict__ Hw)
{
    const int n = blockIdx.x;            // 0..255
    const int k = threadIdx.x;           // 0..255
    split_bf16(W[k * DIM + n], g_WT_hi[n * DIM + k], g_WT_lo[n * DIM + k]);
    g_Hw_f16[n * DIM + k] = __float2half_rn(Hw[n * DIM + k]);
}

// ---------------- K1: h = X @ W (bf16-split mma) + fused epilogue -----------
__global__ __launch_bounds__(256, 2) void k1_mma(const float* __restrict__ X,
                                                 const float* __restrict__ Ws)
{
    extern __shared__ char sm[];
    char* sA_hi = sm;
    char* sA_lo = sm + 9216;
    char* sB_hi = sm + 18432;
    char* sB_lo = sm + 55296;
    __shared__ float s_ws[2][DIM];

    const int t    = threadIdx.x;
    const int lane = t & 31;
    const int wid  = t >> 5;
    const int wm   = wid & 1;
    const int wn   = wid >> 1;
    const int m0   = blockIdx.x * 64;

    s_ws[0][t] = Ws[t];
    s_ws[1][t] = Ws[DIM + t];

    const unsigned lrow = (lane & 15);
    const unsigned lcol = (lane >> 4) << 4;
    const unsigned aBase0 = smem_u32(sA_hi) + (wm * 32 + lrow) * PITCHB + lcol;
    const unsigned bBase0 = smem_u32(sB_hi) + (wn * 64 + lrow) * PITCHB + lcol;

    float acc[2][8][4] = {};

    for (int kc = 0; kc < 4; kc++) {
        const int j0 = kc * 64;
        __syncthreads();
        #pragma unroll
        for (int q = 0; q < 2; q++) {
            const int idx = q * 256 + t;
            const int row = idx >> 3, seg = idx & 7;
            const float* gx = X + (size_t)(m0 + row) * DIM + j0 + seg * 8;
            float4 v0 = *(const float4*)gx;
            float4 v1 = *(const float4*)(gx + 4);
            union { __nv_bfloat16 h[8]; uint4 v; } Uh, Ul;
            split_bf16(v0.x, Uh.h[0], Ul.h[0]);
            split_bf16(v0.y, Uh.h[1], Ul.h[1]);
            split_bf16(v0.z, Uh.h[2], Ul.h[2]);
            split_bf16(v0.w, Uh.h[3], Ul.h[3]);
            split_bf16(v1.x, Uh.h[4], Ul.h[4]);
            split_bf16(v1.y, Uh.h[5], Ul.h[5]);
            split_bf16(v1.z, Uh.h[6], Ul.h[6]);
            split_bf16(v1.w, Uh.h[7], Ul.h[7]);
            const unsigned off = row * PITCHB + seg * 16;
            *(uint4*)(sA_hi + off) = Uh.v;
            *(uint4*)(sA_lo + off) = Ul.v;
        }
        #pragma unroll
        for (int q = 0; q < 8; q++) {
            const int idx = q * 256 + t;
            const int d = idx >> 3, seg = idx & 7;
            const size_t go = (size_t)d * DIM + j0 + seg * 8;
            const unsigned off = d * PITCHB + seg * 16;
            *(uint4*)(sB_hi + off) = *(const uint4*)(g_WT_hi + go);
            *(uint4*)(sB_lo + off) = *(const uint4*)(g_WT_lo + go);
        }
        __syncthreads();
        #pragma unroll
        for (int ks = 0; ks < 4; ks++) {
            unsigned ah[2][4], al[2][4];
            #pragma unroll
            for (int mt = 0; mt < 2; mt++) {
                ldsm_x4(ah[mt], aBase0 + mt * 16 * PITCHB + ks * 32);
                ldsm_x4(al[mt], aBase0 + 9216u + mt * 16 * PITCHB + ks * 32);
            }
            #pragma unroll
            for (int np = 0; np < 4; np++) {
                unsigned bh[4], bl[4];
                ldsm_x4(bh, bBase0 + np * 16 * PITCHB + ks * 32);
                ldsm_x4(bl, bBase0 + 36864u + np * 16 * PITCHB + ks * 32);
                #pragma unroll
                for (int mt = 0; mt < 2; mt++) {
                    mma_bf16(acc[mt][np*2+0], ah[mt], bh[0], bh[2]);
                    mma_bf16(acc[mt][np*2+1], ah[mt], bh[1], bh[3]);
                    mma_bf16(acc[mt][np*2+0], ah[mt], bl[0], bl[2]);
                    mma_bf16(acc[mt][np*2+1], ah[mt], bl[1], bl[3]);
                    mma_bf16(acc[mt][np*2+0], al[mt], bh[0], bh[2]);
                    mma_bf16(acc[mt][np*2+1], al[mt], bh[1], bh[3]);
                }
            }
        }
    }

    // ---- fused epilogue ----
    __syncthreads();
    __half* smT   = (__half*)sm;              // [col][row], pitch 72 halves
    float* partS  = (float*)(sm + 36864);
    float* partD  = (float*)(sm + 40960);

    float ps[2][2] = {}, pd[2][2] = {};
    #pragma unroll
    for (int mt = 0; mt < 2; mt++) {
        const int rA = wm * 32 + mt * 16 + (lane >> 2);
        const int rB = rA + 8;
        #pragma unroll
        for (int nf = 0; nf < 8; nf++) {
            const int c0 = wn * 64 + nf * 8 + (lane & 3) * 2;
            smT[(c0    ) * 72 + rA] = __float2half_rn(acc[mt][nf][0]);
            smT[(c0 + 1) * 72 + rA] = __float2half_rn(acc[mt][nf][1]);
            smT[(c0    ) * 72 + rB] = __float2half_rn(acc[mt][nf][2]);
            smT[(c0 + 1) * 72 + rB] = __float2half_rn(acc[mt][nf][3]);
            ps[mt][0] += acc[mt][nf][0] * s_ws[0][c0] + acc[mt][nf][1] * s_ws[0][c0 + 1];
            pd[mt][0] += acc[mt][nf][0] * s_ws[1][c0] + acc[mt][nf][1] * s_ws[1][c0 + 1];
            ps[mt][1] += acc[mt][nf][2] * s_ws[0][c0] + acc[mt][nf][3] * s_ws[0][c0 + 1];
            pd[mt][1] += acc[mt][nf][2] * s_ws[1][c0] + acc[mt][nf][3] * s_ws[1][c0 + 1];
        }
        const int slot = wn * 4 + (lane & 3);
        partS[rA * 16 + slot] = ps[mt][0];
        partD[rA * 16 + slot] = pd[mt][0];
        partS[rB * 16 + slot] = ps[mt][1];
        partD[rB * 16 + slot] = pd[mt][1];
    }
    __syncthreads();

    {
        const int b  = m0 >> 11;
        const int j0 = m0 & 2047;
        const int colg = t >> 3, seg = t & 7;
        #pragma unroll
        for (int k = 0; k < 8; k++) {
            const int col = colg + k * 32;
            uint4 v = *(const uint4*)((const char*)smT + col * 144 + seg * 16);
            *(uint4*)(g_hT + ((size_t)(b * DIM + col)) * NSEQ + j0 + seg * 8) = v;
        }
    }
    if (t < 64) {
        float s = 0.f, d = 0.f;
        #pragma unroll
        for (int k = 0; k < 16; k++) { s += partS[t * 16 + k]; d += partD[t * 16 + k]; }
        g_asrc[m0 + t] = s;
        g_adst[m0 + t] = d;
    }
}

// ---------------- K3: write I_A + full softmax P (single fp16) --------------
__global__ __launch_bounds__(256) void k3_ia_p(const int*   __restrict__ adj,
                                               const float* __restrict__ bsv,
                                               float*       __restrict__ outIA)
{
    const int i = blockIdx.x;
    const int b = blockIdx.y;
    const int t = threadIdx.x;
    const int lane = t & 31, warp = t >> 5;
    const int j0 = t * 8;
    const size_t rbase = ((size_t)b * NSEQ + i) * NSEQ;
    const float asrc = g_asrc[b * NSEQ + i];
    const float bs0  = bsv[0];

    int4 a0 = *(const int4*)(adj + rbase + j0);
    int4 a1 = *(const int4*)(adj + rbase + j0 + 4);
    const int av[8] = {a0.x, a0.y, a0.z, a0.w, a1.x, a1.y, a1.z, a1.w};
    float ad[8];
    *(float4*)(ad)     = *(const float4*)(g_adst + b * NSEQ + j0);
    *(float4*)(ad + 4) = *(const float4*)(g_adst + b * NSEQ + j0 + 4);

    float sc[8], iav[8];
    float mx = -3.0e38f;
    #pragma unroll
    for (int e = 0; e < 8; e++) {
        const int j = j0 + e;
        float x = asrc + ad[e] + bs0;
        float attn = (j < i) ? fsigmoid(x) : 0.0f;
        float ia = ((j == i) ? 1.0f : 0.0f) - attn;
        iav[e] = ia;
        float s = ((j <= i) && (av[e] == 1)) ? ia : NEGV;
        sc[e] = s;
        mx = fmaxf(mx, s);
    }
    *(float4*)(outIA + rbase + j0)     = *(float4*)(iav);
    *(float4*)(outIA + rbase + j0 + 4) = *(float4*)(iav + 4);

    __shared__ float redm[8], reds[8];
    #pragma unroll
    for (int o = 16; o > 0; o >>= 1) mx = fmaxf(mx, __shfl_xor_sync(0xffffffffu, mx, o));
    if (lane == 0) redm[warp] = mx;
    __syncthreads();
    float bm = redm[0];
    #pragma unroll
    for (int w = 1; w < 8; w++) bm = fmaxf(bm, redm[w]);

    float ex[8];
    float sum = 0.f;
    #pragma unroll
    for (int e = 0; e < 8; e++) { ex[e] = __expf(sc[e] - bm); sum += ex[e]; }
    #pragma unroll
    for (int o = 16; o > 0; o >>= 1) sum += __shfl_xor_sync(0xffffffffu, sum, o);
    if (lane == 0) reds[warp] = sum;
    __syncthreads();
    float tot = 0.f;
    #pragma unroll
    for (int w = 0; w < 8; w++) tot += reds[w];
    const float inv = __fdividef(1.0f, tot);

    union { __half h[8]; uint4 v; } Up;
    #pragma unroll
    for (int e = 0; e < 8; e++) Up.h[e] = __float2half_rn(ex[e] * inv);
    *(uint4*)(g_P + rbase + j0) = Up.v;
}

// ---------------- K4: feat_out = P @ h + b — fp16 GEMM, 3-stage pipeline ----
// (R14 config — best measured: M=128, N=256, 512 thr, one barrier per chunk.)
#define KCH    64
#define BUF_SZ 55296u
#define NCHUNK (NSEQ / KCH)
__device__ __forceinline__ void k4_prefetch(int b, int i0, int j0, unsigned sb)
{
    const int t = threadIdx.x;
    #pragma unroll
    for (int q = 0; q < 2; q++) {
        const int idx = q * 512 + t;
        const int row = idx >> 3, seg = idx & 7;
        const size_t go = ((size_t)(b * NSEQ + i0 + row)) * NSEQ + j0 + seg * 8;
        cp_async16(sb + row * PITCHB + seg * 16, g_P + go);
    }
    #pragma unroll
    for (int q = 0; q < 4; q++) {
        const int idx = q * 512 + t;
        const int d = idx >> 3, seg = idx & 7;
        const size_t go = ((size_t)(b * DIM + d)) * NSEQ + j0 + seg * 8;
        cp_async16(sb + 18432u + d * PITCHB + seg * 16, g_hT + go);
    }
}

__global__ __launch_bounds__(512, 1) void k4_mma(const float* __restrict__ bias,
                                                 float*       __restrict__ outFO)
{
    extern __shared__ char sm[];
    const int t    = threadIdx.x;
    const int lane = t & 31;
    const int wid  = t >> 5;
    const int wm   = wid & 3;
    const int wn   = wid >> 2;
    const int b    = blockIdx.y;
    const int i0   = blockIdx.x * 128;

    const unsigned smb  = smem_u32(sm);
    const unsigned lrow = (lane & 15);
    const unsigned lcol = (lane >> 4) << 4;
    const unsigned aBase0 = smb + (wm * 32 + lrow) * PITCHB + lcol;
    const unsigned bBase0 = smb + 18432u + (wn * 64 + lrow) * PITCHB + lcol;

    float acc[2][8][4] = {};

    k4_prefetch(b, i0, 0, smb);
    CP_COMMIT();
    k4_prefetch(b, i0, KCH, smb + BUF_SZ);
    CP_COMMIT();

    for (int c = 0; c < NCHUNK; c++) {
        if (c == NCHUNK - 1) { CP_WAIT(0); } else { CP_WAIT(1); }
        __syncthreads();                       // chunk c visible to all warps

        const unsigned bufOff = (unsigned)(c % 3) * BUF_SZ;
        #pragma unroll
        for (int ks = 0; ks < 4; ks++) {
            unsigned ah[2][4];
            #pragma unroll
            for (int mt = 0; mt < 2; mt++)
                ldsm_x4(ah[mt], aBase0 + bufOff + mt * 16 * PITCHB + ks * 32);
            #pragma unroll
            for (int np = 0; np < 4; np++) {
                unsigned bh[4];
                ldsm_x4(bh, bBase0 + bufOff + np * 16 * PITCHB + ks * 32);
                #pragma unroll
                for (int mt = 0; mt < 2; mt++) {
                    mma_f16(acc[mt][np*2+0], ah[mt], bh[0], bh[2]);
                    mma_f16(acc[mt][np*2+1], ah[mt], bh[1], bh[3]);
                }
            }
        }

        if (c + 2 < NCHUNK) {                  // overwrites buf (c-1)%3: safe
            k4_prefetch(b, i0, (c + 2) * KCH, smb + (unsigned)((c + 2) % 3) * BUF_SZ);
            CP_COMMIT();
        }
    }

    #pragma unroll
    for (int mt = 0; mt < 2; mt++) {
        const int row0 = i0 + wm * 32 + mt * 16 + (lane >> 2);
        #pragma unroll
        for (int nf = 0; nf < 8; nf++) {
            const int col = wn * 64 + nf * 8 + (lane & 3) * 2;
            const float b0 = bias[col], b1 = bias[col + 1];
            float2 v0 = make_float2(acc[mt][nf][0] + b0, acc[mt][nf][1] + b1);
            float2 v1 = make_float2(acc[mt][nf][2] + b0, acc[mt][nf][3] + b1);
            *(float2*)(outFO + ((size_t)(b * NSEQ + row0)) * DIM + col) = v0;
            *(float2*)(outFO + ((size_t)(b * NSEQ + row0 + 8)) * DIM + col) = v1;
        }
    }
}

// ---------------- K5: gate = sigmoid(X@Hw^T+Hb) — single fp16 product -------
// A = X (fp16 on the fly), B = Hw fp16. SMEM: A 9216 @0, B 36864 @9216.
__global__ __launch_bounds__(256, 2) void k5_mma(const float* __restrict__ X,
                                                 const float* __restrict__ Hb,
                                                 float*       __restrict__ out)
{
    extern __shared__ char sm[];
    char* sA = sm;
    char* sB = sm + 9216;

    const int t    = threadIdx.x;
    const int lane = t & 31;
    const int wid  = t >> 5;
    const int wm   = wid & 1;
    const int wn   = wid >> 1;
    const int m0   = blockIdx.x * 64;

    const unsigned lrow = (lane & 15);
    const unsigned lcol = (lane >> 4) << 4;
    const unsigned aBase0 = smem_u32(sA) + (wm * 32 + lrow) * PITCHB + lcol;
    const unsigned bBase0 = smem_u32(sB) + (wn * 64 + lrow) * PITCHB + lcol;

    float acc[2][8][4] = {};

    for (int kc = 0; kc < 4; kc++) {
        const int j0 = kc * 64;
        __syncthreads();
        // A tile 64x64: X fp32 -> fp16 on the fly
        #pragma unroll
        for (int q = 0; q < 2; q++) {
            const int idx = q * 256 + t;
            const int row = idx >> 3, seg = idx & 7;
            const float* gx = X + (size_t)(m0 + row) * DIM + j0 + seg * 8;
            float4 v0 = *(const float4*)gx;
            float4 v1 = *(const float4*)(gx + 4);
            union { __half h[8]; uint4 v; } U;
            U.h[0] = __float2half_rn(v0.x);
            U.h[1] = __float2half_rn(v0.y);
            U.h[2] = __float2half_rn(v0.z);
            U.h[3] = __float2half_rn(v0.w);
            U.h[4] = __float2half_rn(v1.x);
            U.h[5] = __float2half_rn(v1.y);
            U.h[6] = __float2half_rn(v1.z);
            U.h[7] = __float2half_rn(v1.w);
            *(uint4*)(sA + row * PITCHB + seg * 16) = U.v;
        }
        // B tile 256x64 fp16
        #pragma unroll
        for (int q = 0; q < 8; q++) {
            const int idx = q * 256 + t;
            const int d = idx >> 3, seg = idx & 7;
            const size_t go = (size_t)d * DIM + j0 + seg * 8;
            *(uint4*)(sB + d * PITCHB + seg * 16) = *(const uint4*)(g_Hw_f16 + go);
        }
        __syncthreads();
        #pragma unroll
        for (int ks = 0; ks < 4; ks++) {
            unsigned ah[2][4];
            #pragma unroll
            for (int mt = 0; mt < 2; mt++)
                ldsm_x4(ah[mt], aBase0 + mt * 16 * PITCHB + ks * 32);
            #pragma unroll
            for (int np = 0; np < 4; np++) {
                unsigned bh[4];
                ldsm_x4(bh, bBase0 + np * 16 * PITCHB + ks * 32);
                #pragma unroll
                for (int mt = 0; mt < 2; mt++) {
                    mma_f16(acc[mt][np*2+0], ah[mt], bh[0], bh[2]);
                    mma_f16(acc[mt][np*2+1], ah[mt], bh[1], bh[3]);
                }
            }
        }
    }

    // epilogue: gate + elu + blend (out holds feat_out pre-activation)
    #pragma unroll
    for (int mt = 0; mt < 2; mt++) {
        const int row0 = m0 + wm * 32 + mt * 16 + (lane >> 2);
        #pragma unroll
        for (int nf = 0; nf < 8; nf++) {
            const int col = wn * 64 + nf * 8 + (lane & 3) * 2;
            const float hb0 = Hb[col], hb1 = Hb[col + 1];
            #pragma unroll
            for (int rr = 0; rr < 2; rr++) {
                const size_t o = (size_t)(row0 + rr * 8) * DIM + col;
                float2 fo = *(const float2*)(out + o);
                float2 xv = *(const float2*)(X + o);
                float g0 = fsigmoid(acc[mt][nf][rr*2+0] + hb0);
                float g1 = fsigmoid(acc[mt][nf][rr*2+1] + hb1);
                float e0 = (fo.x > 0.0f) ? fo.x : expm1f(fo.x);
                float e1 = (fo.y > 0.0f) ? fo.y : expm1f(fo.y);
                float2 r;
                r.x = g0 * e0 + (1.0f - g0) * xv.x;
                r.y = g1 * e1 + (1.0f - g1) * xv.y;
                *(float2*)(out + o) = r;
            }
        }
    }
}

// ---------------- launch ----------------------------------------------------
extern "C" void kernel_launch(void* const* d_in, const int* in_sizes, int n_in,
                              void* d_out, int out_size)
{
    const float* feat = (const float*)d_in[0];
    const int*   adj  = (const int*)  d_in[1];
    const float* W    = (const float*)d_in[2];
    const float* bvec = (const float*)d_in[3];
    const float* Ws   = (const float*)d_in[4];
    const float* bs   = (const float*)d_in[5];
    const float* Hw   = (const float*)d_in[6];
    const float* Hb   = (const float*)d_in[7];

    float* out   = (float*)d_out;                      // (B,N,256)
    float* outIA = out + (size_t)NROWS * DIM;          // (B,1,N,N)

    cudaFuncSetAttribute(k1_mma, cudaFuncAttributeMaxDynamicSharedMemorySize, 92160);
    cudaFuncSetAttribute(k4_mma, cudaFuncAttributeMaxDynamicSharedMemorySize, 3 * BUF_SZ);
    cudaFuncSetAttribute(k5_mma, cudaFuncAttributeMaxDynamicSharedMemorySize, 46080);

    k0b_splitW<<<DIM, DIM>>>(W, Hw);
    k1_mma   <<<NROWS / 64, 256, 92160>>>(feat, Ws);
    k3_ia_p  <<<dim3(NSEQ, BATCH), 256>>>(adj, bs, outIA);
    k4_mma   <<<dim3(NSEQ / 128, BATCH), 512, 3 * BUF_SZ>>>(bvec, out);
    k5_mma   <<<NROWS / 64, 256, 46080>>>(feat, Hb, out);
}

// round 17
// speedup vs baseline: 1.1609x; 1.0421x over previous
#include <cuda_runtime.h>
#include <cuda_bf16.h>
#include <cuda_fp16.h>

#define BATCH 8
#define NSEQ  2048
#define DIM   256
#define NROWS (BATCH * NSEQ)          // 16384
#define NEGV  (-999999.0f)

// ---------------- scratch (device globals; no allocation allowed) ----------
__device__ __half g_hT[(size_t)NROWS * DIM];            // h^T fp16 [b][d][j]
__device__ __half g_WT_f16[DIM * DIM];                  // W^T fp16   [n][k]
__device__ __half g_Hw_f16[DIM * DIM];                  // Hw fp16    [n][k]
__device__ __half g_P[(size_t)NROWS * NSEQ];            // softmax P fp16 (67MB)
__device__ float g_asrc[NROWS];
__device__ float g_adst[NROWS];

__device__ __forceinline__ float fsigmoid(float x) {
    return __fdividef(1.0f, 1.0f + __expf(-x));
}

__device__ __forceinline__ unsigned smem_u32(const void* p) {
    unsigned a;
    asm("{ .reg .u64 t; cvta.to.shared.u64 t, %1; cvt.u32.u64 %0, t; }"
        : "=r"(a) : "l"(p));
    return a;
}

__device__ __forceinline__ void ldsm_x4(unsigned r[4], unsigned addr) {
    asm volatile("ldmatrix.sync.aligned.m8n8.x4.shared.b16 {%0,%1,%2,%3}, [%4];"
                 : "=r"(r[0]), "=r"(r[1]), "=r"(r[2]), "=r"(r[3]) : "r"(addr));
}

__device__ __forceinline__ void mma_f16(float c[4], const unsigned a[4],
                                        unsigned b0, unsigned b1) {
    asm volatile("mma.sync.aligned.m16n8k16.row.col.f32.f16.f16.f32 "
                 "{%0,%1,%2,%3}, {%4,%5,%6,%7}, {%8,%9}, {%0,%1,%2,%3};"
                 : "+f"(c[0]), "+f"(c[1]), "+f"(c[2]), "+f"(c[3])
                 : "r"(a[0]), "r"(a[1]), "r"(a[2]), "r"(a[3]), "r"(b0), "r"(b1));
}

__device__ __forceinline__ void split_f16(float v, __half& hi, __half& lo) {
    hi = __float2half_rn(v);
    lo = __float2half_rn(v - __half2float(hi));
}

__device__ __forceinline__ void cp_async16(unsigned saddr, const void* gptr) {
    asm volatile("cp.async.cg.shared.global [%0], [%1], 16;"
                 :: "r"(saddr), "l"(gptr) : "memory");
}
#define CP_COMMIT() asm volatile("cp.async.commit_group;" ::: "memory")
#define CP_WAIT(N)  asm volatile("cp.async.wait_group %0;" :: "n"(N) : "memory")

#define PITCHB 144

// ---------------- K0b: W^T fp16 + Hw fp16 -----------------------------------
__global__ __launch_bounds__(256) void k0b_splitW(const float* __restrict__ W,
                                                  const float* __restrict__ Hw)
{
    const int n = blockIdx.x;            // 0..255
    const int k = threadIdx.x;           // 0..255
    g_WT_f16[n * DIM + k] = __float2half_rn(W[k * DIM + n]);
    g_Hw_f16[n * DIM + k] = __float2half_rn(Hw[n * DIM + k]);
}

// ---------------- K1: h = X @ W (fp16 2-product mma) + fused epilogue -------
// A = X split fp16 hi/lo (on the fly), B = W^T single fp16.
// SMEM: A_hi @0 (9216), A_lo @9216, B @18432 (36864); total 55296.
__global__ __launch_bounds__(256, 2) void k1_mma(const float* __restrict__ X,
                                                 const float* __restrict__ Ws)
{
    extern __shared__ char sm[];
    char* sA_hi = sm;
    char* sA_lo = sm + 9216;
    char* sB    = sm + 18432;
    __shared__ float s_ws[2][DIM];

    const int t    = threadIdx.x;
    const int lane = t & 31;
    const int wid  = t >> 5;
    const int wm   = wid & 1;
    const int wn   = wid >> 1;
    const int m0   = blockIdx.x * 64;

    s_ws[0][t] = Ws[t];
    s_ws[1][t] = Ws[DIM + t];

    const unsigned lrow = (lane & 15);
    const unsigned lcol = (lane >> 4) << 4;
    const unsigned aBase0 = smem_u32(sA_hi) + (wm * 32 + lrow) * PITCHB + lcol;
    const unsigned bBase0 = smem_u32(sB) + (wn * 64 + lrow) * PITCHB + lcol;

    float acc[2][8][4] = {};

    for (int kc = 0; kc < 4; kc++) {
        const int j0 = kc * 64;
        __syncthreads();
        // A tile 64x64: read X fp32, split fp16 hi/lo on the fly
        #pragma unroll
        for (int q = 0; q < 2; q++) {
            const int idx = q * 256 + t;
            const int row = idx >> 3, seg = idx & 7;
            const float* gx = X + (size_t)(m0 + row) * DIM + j0 + seg * 8;
            float4 v0 = *(const float4*)gx;
            float4 v1 = *(const float4*)(gx + 4);
            union { __half h[8]; uint4 v; } Uh, Ul;
            split_f16(v0.x, Uh.h[0], Ul.h[0]);
            split_f16(v0.y, Uh.h[1], Ul.h[1]);
            split_f16(v0.z, Uh.h[2], Ul.h[2]);
            split_f16(v0.w, Uh.h[3], Ul.h[3]);
            split_f16(v1.x, Uh.h[4], Ul.h[4]);
            split_f16(v1.y, Uh.h[5], Ul.h[5]);
            split_f16(v1.z, Uh.h[6], Ul.h[6]);
            split_f16(v1.w, Uh.h[7], Ul.h[7]);
            const unsigned off = row * PITCHB + seg * 16;
            *(uint4*)(sA_hi + off) = Uh.v;
            *(uint4*)(sA_lo + off) = Ul.v;
        }
        // B tile 256x64 from fp16 W^T
        #pragma unroll
        for (int q = 0; q < 8; q++) {
            const int idx = q * 256 + t;
            const int d = idx >> 3, seg = idx & 7;
            const size_t go = (size_t)d * DIM + j0 + seg * 8;
            *(uint4*)(sB + d * PITCHB + seg * 16) = *(const uint4*)(g_WT_f16 + go);
        }
        __syncthreads();
        #pragma unroll
        for (int ks = 0; ks < 4; ks++) {
            unsigned ah[2][4], al[2][4];
            #pragma unroll
            for (int mt = 0; mt < 2; mt++) {
                ldsm_x4(ah[mt], aBase0 + mt * 16 * PITCHB + ks * 32);
                ldsm_x4(al[mt], aBase0 + 9216u + mt * 16 * PITCHB + ks * 32);
            }
            #pragma unroll
            for (int np = 0; np < 4; np++) {
                unsigned bh[4];
                ldsm_x4(bh, bBase0 + np * 16 * PITCHB + ks * 32);
                #pragma unroll
                for (int mt = 0; mt < 2; mt++) {
                    mma_f16(acc[mt][np*2+0], ah[mt], bh[0], bh[2]);   // X_hi * W
                    mma_f16(acc[mt][np*2+1], ah[mt], bh[1], bh[3]);
                    mma_f16(acc[mt][np*2+0], al[mt], bh[0], bh[2]);   // X_lo * W
                    mma_f16(acc[mt][np*2+1], al[mt], bh[1], bh[3]);
                }
            }
        }
    }

    // ---- fused epilogue ----
    __syncthreads();
    __half* smT   = (__half*)sm;              // [col][row], pitch 72 halves
    float* partS  = (float*)(sm + 36864);
    float* partD  = (float*)(sm + 40960);

    float ps[2][2] = {}, pd[2][2] = {};
    #pragma unroll
    for (int mt = 0; mt < 2; mt++) {
        const int rA = wm * 32 + mt * 16 + (lane >> 2);
        const int rB = rA + 8;
        #pragma unroll
        for (int nf = 0; nf < 8; nf++) {
            const int c0 = wn * 64 + nf * 8 + (lane & 3) * 2;
            smT[(c0    ) * 72 + rA] = __float2half_rn(acc[mt][nf][0]);
            smT[(c0 + 1) * 72 + rA] = __float2half_rn(acc[mt][nf][1]);
            smT[(c0    ) * 72 + rB] = __float2half_rn(acc[mt][nf][2]);
            smT[(c0 + 1) * 72 + rB] = __float2half_rn(acc[mt][nf][3]);
            ps[mt][0] += acc[mt][nf][0] * s_ws[0][c0] + acc[mt][nf][1] * s_ws[0][c0 + 1];
            pd[mt][0] += acc[mt][nf][0] * s_ws[1][c0] + acc[mt][nf][1] * s_ws[1][c0 + 1];
            ps[mt][1] += acc[mt][nf][2] * s_ws[0][c0] + acc[mt][nf][3] * s_ws[0][c0 + 1];
            pd[mt][1] += acc[mt][nf][2] * s_ws[1][c0] + acc[mt][nf][3] * s_ws[1][c0 + 1];
        }
        const int slot = wn * 4 + (lane & 3);
        partS[rA * 16 + slot] = ps[mt][0];
        partD[rA * 16 + slot] = pd[mt][0];
        partS[rB * 16 + slot] = ps[mt][1];
        partD[rB * 16 + slot] = pd[mt][1];
    }
    __syncthreads();

    {
        const int b  = m0 >> 11;
        const int j0 = m0 & 2047;
        const int colg = t >> 3, seg = t & 7;
        #pragma unroll
        for (int k = 0; k < 8; k++) {
            const int col = colg + k * 32;
            uint4 v = *(const uint4*)((const char*)smT + col * 144 + seg * 16);
            *(uint4*)(g_hT + ((size_t)(b * DIM + col)) * NSEQ + j0 + seg * 8) = v;
        }
    }
    if (t < 64) {
        float s = 0.f, d = 0.f;
        #pragma unroll
        for (int k = 0; k < 16; k++) { s += partS[t * 16 + k]; d += partD[t * 16 + k]; }
        g_asrc[m0 + t] = s;
        g_adst[m0 + t] = d;
    }
}

// ---------------- K3: write I_A + full softmax P (single fp16) --------------
__global__ __launch_bounds__(256) void k3_ia_p(const int*   __restrict__ adj,
                                               const float* __restrict__ bsv,
                                               float*       __restrict__ outIA)
{
    const int i = blockIdx.x;
    const int b = blockIdx.y;
    const int t = threadIdx.x;
    const int lane = t & 31, warp = t >> 5;
    const int j0 = t * 8;
    const size_t rbase = ((size_t)b * NSEQ + i) * NSEQ;
    const float asrc = g_asrc[b * NSEQ + i];
    const float bs0  = bsv[0];

    int4 a0 = *(const int4*)(adj + rbase + j0);
    int4 a1 = *(const int4*)(adj + rbase + j0 + 4);
    const int av[8] = {a0.x, a0.y, a0.z, a0.w, a1.x, a1.y, a1.z, a1.w};
    float ad[8];
    *(float4*)(ad)     = *(const float4*)(g_adst + b * NSEQ + j0);
    *(float4*)(ad + 4) = *(const float4*)(g_adst + b * NSEQ + j0 + 4);

    float sc[8], iav[8];
    float mx = -3.0e38f;
    #pragma unroll
    for (int e = 0; e < 8; e++) {
        const int j = j0 + e;
        float x = asrc + ad[e] + bs0;
        float attn = (j < i) ? fsigmoid(x) : 0.0f;
        float ia = ((j == i) ? 1.0f : 0.0f) - attn;
        iav[e] = ia;
        float s = ((j <= i) && (av[e] == 1)) ? ia : NEGV;
        sc[e] = s;
        mx = fmaxf(mx, s);
    }
    *(float4*)(outIA + rbase + j0)     = *(float4*)(iav);
    *(float4*)(outIA + rbase + j0 + 4) = *(float4*)(iav + 4);

    __shared__ float redm[8], reds[8];
    #pragma unroll
    for (int o = 16; o > 0; o >>= 1) mx = fmaxf(mx, __shfl_xor_sync(0xffffffffu, mx, o));
    if (lane == 0) redm[warp] = mx;
    __syncthreads();
    float bm = redm[0];
    #pragma unroll
    for (int w = 1; w < 8; w++) bm = fmaxf(bm, redm[w]);

    float ex[8];
    float sum = 0.f;
    #pragma unroll
    for (int e = 0; e < 8; e++) { ex[e] = __expf(sc[e] - bm); sum += ex[e]; }
    #pragma unroll
    for (int o = 16; o > 0; o >>= 1) sum += __shfl_xor_sync(0xffffffffu, sum, o);
    if (lane == 0) reds[warp] = sum;
    __syncthreads();
    float tot = 0.f;
    #pragma unroll
    for (int w = 0; w < 8; w++) tot += reds[w];
    const float inv = __fdividef(1.0f, tot);

    union { __half h[8]; uint4 v; } Up;
    #pragma unroll
    for (int e = 0; e < 8; e++) Up.h[e] = __float2half_rn(ex[e] * inv);
    *(uint4*)(g_P + rbase + j0) = Up.v;
}

// ---------------- K4: feat_out = P @ h + b — fp16 GEMM, 3-stage pipeline ----
// (R14 config — best measured: M=128, N=256, 512 thr, one barrier per chunk.)
#define KCH    64
#define BUF_SZ 55296u
#define NCHUNK (NSEQ / KCH)
__device__ __forceinline__ void k4_prefetch(int b, int i0, int j0, unsigned sb)
{
    const int t = threadIdx.x;
    #pragma unroll
    for (int q = 0; q < 2; q++) {
        const int idx = q * 512 + t;
        const int row = idx >> 3, seg = idx & 7;
        const size_t go = ((size_t)(b * NSEQ + i0 + row)) * NSEQ + j0 + seg * 8;
        cp_async16(sb + row * PITCHB + seg * 16, g_P + go);
    }
    #pragma unroll
    for (int q = 0; q < 4; q++) {
        const int idx = q * 512 + t;
        const int d = idx >> 3, seg = idx & 7;
        const size_t go = ((size_t)(b * DIM + d)) * NSEQ + j0 + seg * 8;
        cp_async16(sb + 18432u + d * PITCHB + seg * 16, g_hT + go);
    }
}

__global__ __launch_bounds__(512, 1) void k4_mma(const float* __restrict__ bias,
                                                 float*       __restrict__ outFO)
{
    extern __shared__ char sm[];
    const int t    = threadIdx.x;
    const int lane = t & 31;
    const int wid  = t >> 5;
    const int wm   = wid & 3;
    const int wn   = wid >> 2;
    const int b    = blockIdx.y;
    const int i0   = blockIdx.x * 128;

    const unsigned smb  = smem_u32(sm);
    const unsigned lrow = (lane & 15);
    const unsigned lcol = (lane >> 4) << 4;
    const unsigned aBase0 = smb + (wm * 32 + lrow) * PITCHB + lcol;
    const unsigned bBase0 = smb + 18432u + (wn * 64 + lrow) * PITCHB + lcol;

    float acc[2][8][4] = {};

    k4_prefetch(b, i0, 0, smb);
    CP_COMMIT();
    k4_prefetch(b, i0, KCH, smb + BUF_SZ);
    CP_COMMIT();

    for (int c = 0; c < NCHUNK; c++) {
        if (c == NCHUNK - 1) { CP_WAIT(0); } else { CP_WAIT(1); }
        __syncthreads();                       // chunk c visible to all warps

        const unsigned bufOff = (unsigned)(c % 3) * BUF_SZ;
        #pragma unroll
        for (int ks = 0; ks < 4; ks++) {
            unsigned ah[2][4];
            #pragma unroll
            for (int mt = 0; mt < 2; mt++)
                ldsm_x4(ah[mt], aBase0 + bufOff + mt * 16 * PITCHB + ks * 32);
            #pragma unroll
            for (int np = 0; np < 4; np++) {
                unsigned bh[4];
                ldsm_x4(bh, bBase0 + bufOff + np * 16 * PITCHB + ks * 32);
                #pragma unroll
                for (int mt = 0; mt < 2; mt++) {
                    mma_f16(acc[mt][np*2+0], ah[mt], bh[0], bh[2]);
                    mma_f16(acc[mt][np*2+1], ah[mt], bh[1], bh[3]);
                }
            }
        }

        if (c + 2 < NCHUNK) {                  // overwrites buf (c-1)%3: safe
            k4_prefetch(b, i0, (c + 2) * KCH, smb + (unsigned)((c + 2) % 3) * BUF_SZ);
            CP_COMMIT();
        }
    }

    #pragma unroll
    for (int mt = 0; mt < 2; mt++) {
        const int row0 = i0 + wm * 32 + mt * 16 + (lane >> 2);
        #pragma unroll
        for (int nf = 0; nf < 8; nf++) {
            const int col = wn * 64 + nf * 8 + (lane & 3) * 2;
            const float b0 = bias[col], b1 = bias[col + 1];
            float2 v0 = make_float2(acc[mt][nf][0] + b0, acc[mt][nf][1] + b1);
            float2 v1 = make_float2(acc[mt][nf][2] + b0, acc[mt][nf][3] + b1);
            *(float2*)(outFO + ((size_t)(b * NSEQ + row0)) * DIM + col) = v0;
            *(float2*)(outFO + ((size_t)(b * NSEQ + row0 + 8)) * DIM + col) = v1;
        }
    }
}

// ---------------- K5: gate = sigmoid(X@Hw^T+Hb) — single fp16 product -------
__global__ __launch_bounds__(256, 2) void k5_mma(const float* __restrict__ X,
                                                 const float* __restrict__ Hb,
                                                 float*       __restrict__ out)
{
    extern __shared__ char sm[];
    char* sA = sm;
    char* sB = sm + 9216;

    const int t    = threadIdx.x;
    const int lane = t & 31;
    const int wid  = t >> 5;
    const int wm   = wid & 1;
    const int wn   = wid >> 1;
    const int m0   = blockIdx.x * 64;

    const unsigned lrow = (lane & 15);
    const unsigned lcol = (lane >> 4) << 4;
    const unsigned aBase0 = smem_u32(sA) + (wm * 32 + lrow) * PITCHB + lcol;
    const unsigned bBase0 = smem_u32(sB) + (wn * 64 + lrow) * PITCHB + lcol;

    float acc[2][8][4] = {};

    for (int kc = 0; kc < 4; kc++) {
        const int j0 = kc * 64;
        __syncthreads();
        #pragma unroll
        for (int q = 0; q < 2; q++) {
            const int idx = q * 256 + t;
            const int row = idx >> 3, seg = idx & 7;
            const float* gx = X + (size_t)(m0 + row) * DIM + j0 + seg * 8;
            float4 v0 = *(const float4*)gx;
            float4 v1 = *(const float4*)(gx + 4);
            union { __half h[8]; uint4 v; } U;
            U.h[0] = __float2half_rn(v0.x);
            U.h[1] = __float2half_rn(v0.y);
            U.h[2] = __float2half_rn(v0.z);
            U.h[3] = __float2half_rn(v0.w);
            U.h[4] = __float2half_rn(v1.x);
            U.h[5] = __float2half_rn(v1.y);
            U.h[6] = __float2half_rn(v1.z);
            U.h[7] = __float2half_rn(v1.w);
            *(uint4*)(sA + row * PITCHB + seg * 16) = U.v;
        }
        #pragma unroll
        for (int q = 0; q < 8; q++) {
            const int idx = q * 256 + t;
            const int d = idx >> 3, seg = idx & 7;
            const size_t go = (size_t)d * DIM + j0 + seg * 8;
            *(uint4*)(sB + d * PITCHB + seg * 16) = *(const uint4*)(g_Hw_f16 + go);
        }
        __syncthreads();
        #pragma unroll
        for (int ks = 0; ks < 4; ks++) {
            unsigned ah[2][4];
            #pragma unroll
            for (int mt = 0; mt < 2; mt++)
                ldsm_x4(ah[mt], aBase0 + mt * 16 * PITCHB + ks * 32);
            #pragma unroll
            for (int np = 0; np < 4; np++) {
                unsigned bh[4];
                ldsm_x4(bh, bBase0 + np * 16 * PITCHB + ks * 32);
                #pragma unroll
                for (int mt = 0; mt < 2; mt++) {
                    mma_f16(acc[mt][np*2+0], ah[mt], bh[0], bh[2]);
                    mma_f16(acc[mt][np*2+1], ah[mt], bh[1], bh[3]);
                }
            }
        }
    }

    // epilogue: gate + elu + blend (out holds feat_out pre-activation)
    #pragma unroll
    for (int mt = 0; mt < 2; mt++) {
        const int row0 = m0 + wm * 32 + mt * 16 + (lane >> 2);
        #pragma unroll
        for (int nf = 0; nf < 8; nf++) {
            const int col = wn * 64 + nf * 8 + (lane & 3) * 2;
            const float hb0 = Hb[col], hb1 = Hb[col + 1];
            #pragma unroll
            for (int rr = 0; rr < 2; rr++) {
                const size_t o = (size_t)(row0 + rr * 8) * DIM + col;
                float2 fo = *(const float2*)(out + o);
                float2 xv = *(const float2*)(X + o);
                float g0 = fsigmoid(acc[mt][nf][rr*2+0] + hb0);
                float g1 = fsigmoid(acc[mt][nf][rr*2+1] + hb1);
                float e0 = (fo.x > 0.0f) ? fo.x : expm1f(fo.x);
                float e1 = (fo.y > 0.0f) ? fo.y : expm1f(fo.y);
                float2 r;
                r.x = g0 * e0 + (1.0f - g0) * xv.x;
                r.y = g1 * e1 + (1.0f - g1) * xv.y;
                *(float2*)(out + o) = r;
            }
        }
    }
}

// ---------------- launch ----------------------------------------------------
extern "C" void kernel_launch(void* const* d_in, const int* in_sizes, int n_in,
                              void* d_out, int out_size)
{
    const float* feat = (const float*)d_in[0];
    const int*   adj  = (const int*)  d_in[1];
    const float* W    = (const float*)d_in[2];
    const float* bvec = (const float*)d_in[3];
    const float* Ws   = (const float*)d_in[4];
    const float* bs   = (const float*)d_in[5];
    const float* Hw   = (const float*)d_in[6];
    const float* Hb   = (const float*)d_in[7];

    float* out   = (float*)d_out;                      // (B,N,256)
    float* outIA = out + (size_t)NROWS * DIM;          // (B,1,N,N)

    cudaFuncSetAttribute(k1_mma, cudaFuncAttributeMaxDynamicSharedMemorySize, 55296);
    cudaFuncSetAttribute(k4_mma, cudaFuncAttributeMaxDynamicSharedMemorySize, 3 * BUF_SZ);
    cudaFuncSetAttribute(k5_mma, cudaFuncAttributeMaxDynamicSharedMemorySize, 46080);

    k0b_splitW<<<DIM, DIM>>>(W, Hw);
    k1_mma   <<<NROWS / 64, 256, 55296>>>(feat, Ws);
    k3_ia_p  <<<dim3(NSEQ, BATCH), 256>>>(adj, bs, outIA);
    k4_mma   <<<dim3(NSEQ / 128, BATCH), 512, 3 * BUF_SZ>>>(bvec, out);
    k5_mma   <<<NROWS / 64, 256, 46080>>>(feat, Hb, out);
}